// round 7
// baseline (speedup 1.0000x reference)
#include <cuda_runtime.h>
#include <cuda_bf16.h>
#include <cstdint>

#define TILE    128
#define TSTEPS  10
#define HID     50
#define THREADS 512
#define NCTA    1024            // 131072 / 128
#define AST     136             // bf16 elems per A row (68 words; 68%32=4 -> conflict-free afrag)
#define LSCR    (TSTEPS * TILE * HID)   // 64000 floats per CTA, layout [t][m][j]

__device__ float g_scr[(size_t)NCTA * LSCR];

#define WSM_U2     (25 * 8 * 32)          // 6400 uint2 = 51200 B
#define BIAS_OFF   51200
#define A_OFF      52000
#define SMEM_TOTAL (A_OFF + TILE * AST * 2)   // 86816 B

__device__ __forceinline__ float sigmf(float v) {          // accurate (dense head only)
    return __fdividef(1.f, 1.f + __expf(-v));
}
__device__ __forceinline__ float htanh(float v) {          // HW MUFU.TANH
    float r; asm("tanh.approx.f32 %0, %1;" : "=f"(r) : "f"(v)); return r;
}
__device__ __forceinline__ float sigmh(float v) {          // 1 MUFU + 2 fma-pipe ops
    return fmaf(htanh(0.5f * v), 0.5f, 0.5f);
}
__device__ __forceinline__ uint32_t pack_bf2(float lo, float hi) {
    __nv_bfloat162 p = __floats2bfloat162_rn(lo, hi);      // .x = lo = lower 16 bits
    return *reinterpret_cast<uint32_t*>(&p);
}
__device__ __forceinline__ void mma16(float (&d)[4], const uint32_t (&a)[4], uint2 b) {
    asm volatile("mma.sync.aligned.m16n8k16.row.col.f32.bf16.bf16.f32 "
                 "{%0,%1,%2,%3}, {%4,%5,%6,%7}, {%8,%9}, {%0,%1,%2,%3};\n"
                 : "+f"(d[0]), "+f"(d[1]), "+f"(d[2]), "+f"(d[3])
                 : "r"(a[0]), "r"(a[1]), "r"(a[2]), "r"(a[3]), "r"(b.x), "r"(b.y));
}

__device__ __forceinline__ float fetchWU(int k, int sc, const float* W, const float* U, int Fin) {
    if (k < 64) return (k < Fin) ? W[k * 200 + sc] : 0.f;
    int ku = k - 64;
    return (ku < HID) ? U[ku * 200 + sc] : 0.f;
}

// weights pre-permuted into m16n8k16 b-frag order, gate cols permuted col'=4j+q,
// k stacked [W pad64 ; U pad64]; fills permuted bias; zeroes A (pads + h0).
__device__ __forceinline__ void fill_layer_weights(char* smem, const float* __restrict__ W,
                                                   const float* __restrict__ U,
                                                   const float* __restrict__ b,
                                                   int Fin, int tid)
{
    uint2*    wsm   = reinterpret_cast<uint2*>(smem);
    float*    biasp = reinterpret_cast<float*>(smem + BIAS_OFF);
    uint32_t* Az    = reinterpret_cast<uint32_t*>(smem + A_OFF);
    for (int idx = tid; idx < WSM_U2; idx += THREADS) {
        int lane = idx & 31, kt = (idx >> 5) & 7, nt = idx >> 8;
        int colp = nt * 8 + (lane >> 2);
        int sc   = (colp & 3) * HID + (colp >> 2);      // original col q*50+j
        int kb   = kt * 16 + (lane & 3) * 2;
        float v0 = fetchWU(kb,     sc, W, U, Fin);
        float v1 = fetchWU(kb + 1, sc, W, U, Fin);
        float v2 = fetchWU(kb + 8, sc, W, U, Fin);
        float v3 = fetchWU(kb + 9, sc, W, U, Fin);
        wsm[idx] = make_uint2(pack_bf2(v0, v1), pack_bf2(v2, v3));
    }
    for (int c = tid; c < 200; c += THREADS)
        biasp[c] = b[(c & 3) * HID + (c >> 2)];
    for (int idx = tid; idx < TILE * AST / 2; idx += THREADS)
        Az[idx] = 0u;
}

template<bool L0, bool LAST>
__device__ __forceinline__ void run_layer(char* smem, const float* __restrict__ xsrc,
                                          float* __restrict__ scr, int tid)
{
    const uint2*   wsm   = reinterpret_cast<const uint2*>(smem);
    const float*   biasp = reinterpret_cast<const float*>(smem + BIAS_OFF);
    __nv_bfloat16* A     = reinterpret_cast<__nv_bfloat16*>(smem + A_OFF);

    const int lane = tid & 31, wrp = tid >> 5;
    const int g = lane >> 2, lam = lane & 3;
    const int mw = wrp >> 1, ng = wrp & 1;        // 8 M-tiles x 2 N-halves
    const int row0  = mw * 16 + g;
    const int ntbeg = ng ? 13 : 0;
    const int ntend = ng ? 25 : 13;
    const bool hi   = lam & 1;
    const int rowE  = row0 + (hi ? 8 : 0);

    float cst[13];
#pragma unroll
    for (int i = 0; i < 13; ++i) cst[i] = 0.f;

    for (int t = 0; t < TSTEPS; ++t) {
        __syncthreads();                           // prior epilogue / weight-fill writes visible
        if (L0) {
            for (int idx = tid; idx < TILE * 8; idx += THREADS) {
                int m = idx >> 3, f = idx & 7;
                if (f < 5)
                    A[m * AST + f] = __float2bfloat16_rn(xsrc[m * 50 + t * 5 + f]);
            }
        } else {
            // [t][m][j] scratch: coalesced LDG, consecutive bf16 STS (conflict-free)
            const float* sp = scr + t * (TILE * HID);
            for (int idx = tid; idx < TILE * 64; idx += THREADS) {
                int m = idx >> 6, j = idx & 63;
                if (j < HID)
                    A[m * AST + j] = __float2bfloat16_rn(sp[m * HID + j]);
            }
        }
        __syncthreads();

        // hoist a-fragments (L0: only k-tiles {0,4..7} nonzero)
        uint32_t af[8][4];
#pragma unroll
        for (int kt = 0; kt < 8; ++kt) {
            if (L0 && kt >= 1 && kt <= 3) continue;
            const __nv_bfloat16* ap = A + kt * 16 + lam * 2;
            af[kt][0] = *reinterpret_cast<const uint32_t*>(ap + row0 * AST);
            af[kt][1] = *reinterpret_cast<const uint32_t*>(ap + (row0 + 8) * AST);
            af[kt][2] = *reinterpret_cast<const uint32_t*>(ap + row0 * AST + 8);
            af[kt][3] = *reinterpret_cast<const uint32_t*>(ap + (row0 + 8) * AST + 8);
        }
        __syncthreads();                           // all a-frag reads done before h rewritten

        for (int nt = ntbeg; nt < ntend; ++nt) {
            float2 bv = *reinterpret_cast<const float2*>(&biasp[nt * 8 + lam * 2]);
            float accA[4] = {bv.x, bv.y, bv.x, bv.y};
            float accB[4] = {0.f, 0.f, 0.f, 0.f};
            const uint2* wp = wsm + nt * 256 + lane;
#pragma unroll
            for (int kt = 0; kt < 8; ++kt) {
                if (L0 && kt >= 1 && kt <= 3) continue;
                uint2 bb = wp[kt * 32];
                if (kt & 1) mma16(accB, af[kt], bb);
                else        mma16(accA, af[kt], bb);
            }
            float a0 = accA[0] + accB[0], a1 = accA[1] + accB[1];
            float a2 = accA[2] + accB[2], a3 = accA[3] + accB[3];
            // pair-exchange: each lane ends owning one (row, unit) with all 4 gates
            float p0 = __shfl_xor_sync(0xffffffffu, a0, 1);
            float p1 = __shfl_xor_sync(0xffffffffu, a1, 1);
            float p2 = __shfl_xor_sync(0xffffffffu, a2, 1);
            float p3 = __shfl_xor_sync(0xffffffffu, a3, 1);
            float zi = hi ? p2 : a0;
            float zf = hi ? p3 : a1;
            float zg = hi ? a2 : p0;
            float zo = hi ? a3 : p1;
            float c  = sigmh(zf) * cst[nt - ntbeg] + sigmh(zi) * htanh(zg);
            cst[nt - ntbeg] = c;
            float h  = sigmh(zo) * htanh(c);
            int unit = nt * 2 + (lam >> 1);
            if (LAST) {
                if (t == TSTEPS - 1) scr[t * (TILE * HID) + rowE * HID + unit] = h;  // fp32 for dense
                else                 A[rowE * AST + 64 + unit] = __float2bfloat16_rn(h);
            } else {
                A[rowE * AST + 64 + unit] = __float2bfloat16_rn(h);
                scr[t * (TILE * HID) + rowE * HID + unit] = h;
            }
        }
    }
}

__global__ void __launch_bounds__(THREADS, 2)
lstm_fused(const float* __restrict__ x,
           const float* __restrict__ W0, const float* __restrict__ U0, const float* __restrict__ B0,
           const float* __restrict__ W1, const float* __restrict__ U1, const float* __restrict__ B1,
           const float* __restrict__ W2, const float* __restrict__ U2, const float* __restrict__ B2,
           const float* __restrict__ W3, const float* __restrict__ U3, const float* __restrict__ B3,
           const float* __restrict__ Wd1, const float* __restrict__ bd1,
           const float* __restrict__ Wd2, const float* __restrict__ bd2,
           float* __restrict__ out)
{
    extern __shared__ char smem[];
    const int tid = threadIdx.x;
    const int cta = blockIdx.x;
    float* scr = g_scr + (size_t)cta * LSCR;

    fill_layer_weights(smem, W0, U0, B0, 5, tid);
    run_layer<true,  false>(smem, x + (size_t)cta * TILE * 50, scr, tid);
    __syncthreads();
    fill_layer_weights(smem, W1, U1, B1, HID, tid);
    run_layer<false, false>(smem, nullptr, scr, tid);
    __syncthreads();
    fill_layer_weights(smem, W2, U2, B2, HID, tid);
    run_layer<false, false>(smem, nullptr, scr, tid);
    __syncthreads();
    fill_layer_weights(smem, W3, U3, B3, HID, tid);
    run_layer<false, true >(smem, nullptr, scr, tid);
    __syncthreads();

    // fused dense head: out = sigmoid((h @ Wd1 + bd1) @ Wd2 + bd2)
    float* dw = reinterpret_cast<float*>(smem);          // reuse weight region
    for (int idx = tid; idx < 2500; idx += THREADS)
        dw[idx] = Wd1[(idx % 50) * 50 + idx / 50];       // dw[j2*50+j] = Wd1[j][j2]
    if (tid < 50) { dw[2500 + tid] = bd1[tid]; dw[2550 + tid] = Wd2[tid]; }
    if (tid == 0)  dw[2600] = bd2[0];
    __syncthreads();

    if (tid < TILE) {
        const float* hp = scr + 9 * (TILE * HID) + tid * HID;   // layer-4 last h (fp32)
        float h[HID];
#pragma unroll
        for (int j = 0; j < HID; ++j) h[j] = hp[j];
        float acc2 = dw[2600];
        for (int j2 = 0; j2 < HID; ++j2) {
            float a = dw[2500 + j2];
#pragma unroll
            for (int j = 0; j < HID; ++j) a += h[j] * dw[j2 * 50 + j];
            acc2 += a * dw[2550 + j2];
        }
        out[cta * TILE + tid] = sigmf(acc2);
    }
}

extern "C" void kernel_launch(void* const* d_in, const int* in_sizes, int n_in,
                              void* d_out, int out_size) {
    cudaFuncSetAttribute(lstm_fused, cudaFuncAttributeMaxDynamicSharedMemorySize, SMEM_TOTAL);
    lstm_fused<<<NCTA, THREADS, SMEM_TOTAL>>>(
        (const float*)d_in[0],
        (const float*)d_in[1],  (const float*)d_in[2],  (const float*)d_in[3],
        (const float*)d_in[4],  (const float*)d_in[5],  (const float*)d_in[6],
        (const float*)d_in[7],  (const float*)d_in[8],  (const float*)d_in[9],
        (const float*)d_in[10], (const float*)d_in[11], (const float*)d_in[12],
        (const float*)d_in[13], (const float*)d_in[14],
        (const float*)d_in[15], (const float*)d_in[16],
        (float*)d_out);
}

// round 8
// speedup vs baseline: 1.3152x; 1.3152x over previous
#include <cuda_runtime.h>
#include <cuda_bf16.h>
#include <cstdint>

#define TILE    128
#define TSTEPS  10
#define HID     50
#define THREADS 512
#define NCTA    1024            // 131072 / 128
#define AST     136             // bf16 elems per A row (68 words; 68%32=4 -> conflict-free afrag)
#define LSCR    (TSTEPS * HID * TILE)   // 64000 floats per CTA, layout [t][j][m]

__device__ float g_scr[(size_t)NCTA * LSCR];

#define WSM_U4     (25 * 4 * 32)          // 3200 uint4 = 51200 B
#define BIAS_OFF   51200
#define A_OFF      52000
#define SMEM_TOTAL (A_OFF + TILE * AST * 2)   // 86816 B

__device__ __forceinline__ float sigmf(float v) {
    return __fdividef(1.f, 1.f + __expf(-v));
}
__device__ __forceinline__ float tanha(float v) {
    return 1.f - __fdividef(2.f, __expf(2.f * v) + 1.f);
}
__device__ __forceinline__ uint32_t pack_bf2(float lo, float hi) {
    __nv_bfloat162 p = __floats2bfloat162_rn(lo, hi);      // .x = lo = lower 16 bits
    return *reinterpret_cast<uint32_t*>(&p);
}
__device__ __forceinline__ void mma16(float (&d)[4], const uint32_t (&a)[4],
                                      uint32_t b0, uint32_t b1) {
    asm volatile("mma.sync.aligned.m16n8k16.row.col.f32.bf16.bf16.f32 "
                 "{%0,%1,%2,%3}, {%4,%5,%6,%7}, {%8,%9}, {%0,%1,%2,%3};\n"
                 : "+f"(d[0]), "+f"(d[1]), "+f"(d[2]), "+f"(d[3])
                 : "r"(a[0]), "r"(a[1]), "r"(a[2]), "r"(a[3]), "r"(b0), "r"(b1));
}

__device__ __forceinline__ float fetchWU(int k, int sc, const float* W, const float* U, int Fin) {
    if (k < 64) return (k < Fin) ? W[k * 200 + sc] : 0.f;
    int ku = k - 64;
    return (ku < HID) ? U[ku * 200 + sc] : 0.f;
}

// weights pre-permuted into m16n8k16 b-frag order, gate cols permuted col'=4j+q,
// k stacked [W pad64 ; U pad64]. Paired layout: one uint4 = b-frags of (kt=2a, kt=2a+1).
// Also fills permuted bias; zeroes A (pads + h0).
__device__ __forceinline__ void fill_layer_weights(char* smem, const float* __restrict__ W,
                                                   const float* __restrict__ U,
                                                   const float* __restrict__ b,
                                                   int Fin, int tid)
{
    uint4*    wsm   = reinterpret_cast<uint4*>(smem);
    float*    biasp = reinterpret_cast<float*>(smem + BIAS_OFF);
    uint32_t* Az    = reinterpret_cast<uint32_t*>(smem + A_OFF);
    for (int idx = tid; idx < WSM_U4; idx += THREADS) {
        int lane = idx & 31, kt2 = (idx >> 5) & 3, nt = idx >> 7;
        int colp = nt * 8 + (lane >> 2);
        int sc   = (colp & 3) * HID + (colp >> 2);      // original col q*50+j
        int kb0  = (kt2 * 2) * 16 + (lane & 3) * 2;     // even kt
        int kb1  = kb0 + 16;                            // odd kt
        uint4 w;
        w.x = pack_bf2(fetchWU(kb0,     sc, W, U, Fin), fetchWU(kb0 + 1, sc, W, U, Fin));
        w.y = pack_bf2(fetchWU(kb0 + 8, sc, W, U, Fin), fetchWU(kb0 + 9, sc, W, U, Fin));
        w.z = pack_bf2(fetchWU(kb1,     sc, W, U, Fin), fetchWU(kb1 + 1, sc, W, U, Fin));
        w.w = pack_bf2(fetchWU(kb1 + 8, sc, W, U, Fin), fetchWU(kb1 + 9, sc, W, U, Fin));
        wsm[idx] = w;
    }
    for (int c = tid; c < 200; c += THREADS)
        biasp[c] = b[(c & 3) * HID + (c >> 2)];
    for (int idx = tid; idx < TILE * AST / 2; idx += THREADS)
        Az[idx] = 0u;
}

template<bool L0, bool LAST>
__device__ __forceinline__ void run_layer(char* smem, const float* __restrict__ xsrc,
                                          float* __restrict__ scr, int tid)
{
    const uint4*   wsm   = reinterpret_cast<const uint4*>(smem);
    const float*   biasp = reinterpret_cast<const float*>(smem + BIAS_OFF);
    __nv_bfloat16* A     = reinterpret_cast<__nv_bfloat16*>(smem + A_OFF);

    const int lane = tid & 31, wrp = tid >> 5;
    const int g = lane >> 2, lam = lane & 3;
    const int mw = wrp >> 1, ng = wrp & 1;        // 8 M-tiles x 2 N-halves
    const int row0  = mw * 16 + g;
    const int ntbeg = ng ? 13 : 0;
    const int ntend = ng ? 25 : 13;
    const bool hi   = lam & 1;
    const int rowE  = row0 + (hi ? 8 : 0);

    float cst[13];
#pragma unroll
    for (int i = 0; i < 13; ++i) cst[i] = 0.f;

    __syncthreads();                               // weight-fill / prior-layer writes visible

    for (int t = 0; t < TSTEPS; ++t) {
        // fill input cols of A (disjoint from epilogue h-cols; sync below orders reads)
        if (L0) {
            for (int idx = tid; idx < TILE * 8; idx += THREADS) {
                int m = idx >> 3, f = idx & 7;
                if (f < 5)
                    A[m * AST + f] = __float2bfloat16_rn(xsrc[m * 50 + t * 5 + f]);
            }
        } else {
            const float* sp = scr + t * (HID * TILE);
            for (int idx = tid; idx < TILE * HID; idx += THREADS) {
                int j = idx >> 7, m = idx & 127;
                A[m * AST + j] = __float2bfloat16_rn(sp[j * TILE + m]);
            }
        }
        __syncthreads();

        // hoist a-fragments (L0: only k-tiles {0,4..7} nonzero)
        uint32_t af[8][4];
#pragma unroll
        for (int kt = 0; kt < 8; ++kt) {
            if (L0 && kt >= 1 && kt <= 3) continue;
            const __nv_bfloat16* ap = A + kt * 16 + lam * 2;
            af[kt][0] = *reinterpret_cast<const uint32_t*>(ap + row0 * AST);
            af[kt][1] = *reinterpret_cast<const uint32_t*>(ap + (row0 + 8) * AST);
            af[kt][2] = *reinterpret_cast<const uint32_t*>(ap + row0 * AST + 8);
            af[kt][3] = *reinterpret_cast<const uint32_t*>(ap + (row0 + 8) * AST + 8);
        }
        __syncthreads();                           // all a-frag reads done before h rewritten

        for (int nt = ntbeg; nt < ntend; ++nt) {
            float2 bv = *reinterpret_cast<const float2*>(&biasp[nt * 8 + lam * 2]);
            float accA[4] = {bv.x, bv.y, bv.x, bv.y};
            float accB[4] = {0.f, 0.f, 0.f, 0.f};
            const uint4* wp = wsm + nt * 128 + lane;
#pragma unroll
            for (int kt2 = 0; kt2 < 4; ++kt2) {
                if (L0 && kt2 == 1) continue;               // kt 2,3 are zero x-pad
                uint4 bb = wp[kt2 * 32];
                if (!(L0 && kt2 == 0) || true) {            // even kt -> accA
                    if (!(L0 && false))
                        mma16(accA, af[kt2 * 2], bb.x, bb.y);
                }
                if (!(L0 && kt2 == 0))                      // L0: kt1 is zero x-pad
                    mma16(accB, af[kt2 * 2 + 1], bb.z, bb.w);
            }
            float a0 = accA[0] + accB[0], a1 = accA[1] + accB[1];
            float a2 = accA[2] + accB[2], a3 = accA[3] + accB[3];
            // pair-exchange: each lane ends owning one (row, unit) with all 4 gates
            float p0 = __shfl_xor_sync(0xffffffffu, a0, 1);
            float p1 = __shfl_xor_sync(0xffffffffu, a1, 1);
            float p2 = __shfl_xor_sync(0xffffffffu, a2, 1);
            float p3 = __shfl_xor_sync(0xffffffffu, a3, 1);
            float zi = hi ? p2 : a0;
            float zf = hi ? p3 : a1;
            float zg = hi ? a2 : p0;
            float zo = hi ? a3 : p1;
            float c  = sigmf(zf) * cst[nt - ntbeg] + sigmf(zi) * tanha(zg);
            cst[nt - ntbeg] = c;
            float h  = sigmf(zo) * tanha(c);
            int unit = nt * 2 + (lam >> 1);
            if (LAST) {
                if (t == TSTEPS - 1) scr[(t * HID + unit) * TILE + rowE] = h;  // fp32 for dense
                else                 A[rowE * AST + 64 + unit] = __float2bfloat16_rn(h);
            } else {
                A[rowE * AST + 64 + unit] = __float2bfloat16_rn(h);
                scr[(t * HID + unit) * TILE + rowE] = h;
            }
        }
    }
}

__global__ void __launch_bounds__(THREADS, 2)
lstm_fused(const float* __restrict__ x,
           const float* __restrict__ W0, const float* __restrict__ U0, const float* __restrict__ B0,
           const float* __restrict__ W1, const float* __restrict__ U1, const float* __restrict__ B1,
           const float* __restrict__ W2, const float* __restrict__ U2, const float* __restrict__ B2,
           const float* __restrict__ W3, const float* __restrict__ U3, const float* __restrict__ B3,
           const float* __restrict__ Wd1, const float* __restrict__ bd1,
           const float* __restrict__ Wd2, const float* __restrict__ bd2,
           float* __restrict__ out)
{
    extern __shared__ char smem[];
    const int tid = threadIdx.x;
    const int cta = blockIdx.x;
    float* scr = g_scr + (size_t)cta * LSCR;

    fill_layer_weights(smem, W0, U0, B0, 5, tid);
    run_layer<true,  false>(smem, x + (size_t)cta * TILE * 50, scr, tid);
    __syncthreads();
    fill_layer_weights(smem, W1, U1, B1, HID, tid);
    run_layer<false, false>(smem, nullptr, scr, tid);
    __syncthreads();
    fill_layer_weights(smem, W2, U2, B2, HID, tid);
    run_layer<false, false>(smem, nullptr, scr, tid);
    __syncthreads();
    fill_layer_weights(smem, W3, U3, B3, HID, tid);
    run_layer<false, true >(smem, nullptr, scr, tid);
    __syncthreads();

    // fused dense head: out = sigmoid((h @ Wd1 + bd1) @ Wd2 + bd2)
    float* dw = reinterpret_cast<float*>(smem);          // reuse weight region
    for (int idx = tid; idx < 2500; idx += THREADS)
        dw[idx] = Wd1[(idx % 50) * 50 + idx / 50];       // dw[j2*50+j] = Wd1[j][j2]
    if (tid < 50) { dw[2500 + tid] = bd1[tid]; dw[2550 + tid] = Wd2[tid]; }
    if (tid == 0)  dw[2600] = bd2[0];
    __syncthreads();

    if (tid < TILE) {
        const float* hp = scr + 9 * (HID * TILE) + tid;  // layer-4 last h (fp32, [unit][m])
        float h[HID];
#pragma unroll
        for (int j = 0; j < HID; ++j) h[j] = hp[j * TILE];
        float acc2 = dw[2600];
        for (int j2 = 0; j2 < HID; ++j2) {
            float a = dw[2500 + j2];
#pragma unroll
            for (int j = 0; j < HID; ++j) a += h[j] * dw[j2 * 50 + j];
            acc2 += a * dw[2550 + j2];
        }
        out[cta * TILE + tid] = sigmf(acc2);
    }
}

extern "C" void kernel_launch(void* const* d_in, const int* in_sizes, int n_in,
                              void* d_out, int out_size) {
    cudaFuncSetAttribute(lstm_fused, cudaFuncAttributeMaxDynamicSharedMemorySize, SMEM_TOTAL);
    lstm_fused<<<NCTA, THREADS, SMEM_TOTAL>>>(
        (const float*)d_in[0],
        (const float*)d_in[1],  (const float*)d_in[2],  (const float*)d_in[3],
        (const float*)d_in[4],  (const float*)d_in[5],  (const float*)d_in[6],
        (const float*)d_in[7],  (const float*)d_in[8],  (const float*)d_in[9],
        (const float*)d_in[10], (const float*)d_in[11], (const float*)d_in[12],
        (const float*)d_in[13], (const float*)d_in[14],
        (const float*)d_in[15], (const float*)d_in[16],
        (float*)d_out);
}